// round 1
// baseline (speedup 1.0000x reference)
#include <cuda_runtime.h>

// Problem constants (fixed by the reference)
#define TT 2048
#define BB 32
#define HH 64
#define CELLS (BB * HH)        // 2048 independent cells
#define CHUNK 16               // prefetch chunk (T % CHUNK == 0)

// Parameter physical bounds: smax, k1, k2, kb
// min + (max-min)*u
__global__ __launch_bounds__(32, 1)
void hydro_kernel(const float* __restrict__ forcings,   // [T, CELLS, 2]
                  const float* __restrict__ states0,    // [CELLS, 2]
                  const float* __restrict__ params,     // [CELLS, 4]
                  float* __restrict__ fluxes_out,       // [T, CELLS, 4]
                  float* __restrict__ states_out)       // [T, CELLS, 2]
{
    const int cell = blockIdx.x * blockDim.x + threadIdx.x;
    if (cell >= CELLS) return;

    // ---- parameter transform (once) ----
    const float u0 = params[cell * 4 + 0];
    const float u1 = params[cell * 4 + 1];
    const float u2 = params[cell * 4 + 2];
    const float u3 = params[cell * 4 + 3];
    const float smax = 10.0f   + (500.0f - 10.0f)   * u0;
    const float k1   = 0.01f   + (0.9f   - 0.01f)   * u1;
    const float k2   = 0.001f  + (0.2f   - 0.001f)  * u2;
    const float kb   = 0.001f  + (0.1f   - 0.001f)  * u3;

    const float inv_smax = 1.0f / smax;
    const float c1 = 1.0f - k1 - k2;   // S1 retention factor (excl. ET)
    const float c2 = 1.0f - kb;        // S2 retention factor

    float S1 = states0[cell * 2 + 0];
    float S2 = states0[cell * 2 + 1];

    // strided-by-CELLS views, coalesced across lanes
    const float2* __restrict__ F  = reinterpret_cast<const float2*>(forcings) + cell;
    float4*       __restrict__ FX = reinterpret_cast<float4*>(fluxes_out)     + cell;
    float2*       __restrict__ ST = reinterpret_cast<float2*>(states_out)     + cell;

    // ---- double-buffered register prefetch of forcings ----
    float2 buf[2][CHUNK];
#pragma unroll
    for (int i = 0; i < CHUNK; i++)
        buf[0][i] = F[i * CELLS];

    int pb = 0;
#pragma unroll 1
    for (int c = 0; c < TT / CHUNK; c++) {
        const int tbase = c * CHUNK;

        // prefetch next chunk (independent of state chain)
        if (c + 1 < TT / CHUNK) {
#pragma unroll
            for (int i = 0; i < CHUNK; i++)
                buf[pb ^ 1][i] = F[(tbase + CHUNK + i) * CELLS];
        }

#pragma unroll
        for (int i = 0; i < CHUNK; i++) {
            const float P   = buf[pb][i].x;
            const float PET = buf[pb][i].y;

            // fluxes (S1 >= 0 always -> lower clip unnecessary)
            const float frac = fminf(S1 * inv_smax, 1.0f);
            const float et   = PET * frac;
            const float q1   = k1 * S1;
            const float perc = k2 * S1;
            const float qb   = kb * S2;

            const int t = tbase + i;
            FX[t * CELLS] = make_float4(et, q1, perc, qb);

            // state update + clamp(min=0)
            // S1 + P - et - q1 - perc == fma(S1, 1-k1-k2, P) - et
            S1 = fmaxf(fmaf(S1, c1, P) - et, 0.0f);
            // S2 + perc - qb == fma(S2, 1-kb, perc)
            S2 = fmaxf(fmaf(S2, c2, perc), 0.0f);

            ST[t * CELLS] = make_float2(S1, S2);
        }
        pb ^= 1;
    }
}

extern "C" void kernel_launch(void* const* d_in, const int* in_sizes, int n_in,
                              void* d_out, int out_size)
{
    const float* forcings = (const float*)d_in[0];   // [T,B,H,2]
    const float* states0  = (const float*)d_in[1];   // [B,H,2]
    const float* params   = (const float*)d_in[2];   // [B,H,4]

    float* out = (float*)d_out;
    float* fluxes_out = out;                                   // [T,B,H,4]
    float* states_out = out + (size_t)TT * CELLS * 4;          // [T,B,H,2]

    // 64 blocks x 32 threads: one warp per SM on 64 SMs
    hydro_kernel<<<CELLS / 32, 32>>>(forcings, states0, params,
                                     fluxes_out, states_out);
}

// round 2
// speedup vs baseline: 1.0441x; 1.0441x over previous
#include <cuda_runtime.h>

// Problem constants (fixed by the reference)
#define TT 2048
#define CELLS 2048            // B*H = 32*64 independent cells
#define CHUNK 16              // forcing prefetch chunk (TT % CHUNK == 0)

// ---------------------------------------------------------------------------
// Kernel A: serial state scan. One thread per cell. Writes ONLY states_seq.
// Critical chain per step (S1): FMUL -> FMNMX -> FADD -> FMNMX  (~20 cyc)
//   et = min(S1 * (PET*inv_smax), PET)           (PET*inv off-chain)
//   S1' = max(fma(S1, 1-k1-k2, P) - et, 0)
//   S2' = max(fma(S2, 1-kb, k2*S1), 0)           (parallel side chain)
// ---------------------------------------------------------------------------
__global__ __launch_bounds__(32, 1)
void scan_kernel(const float* __restrict__ forcings,   // [T, CELLS, 2]
                 const float* __restrict__ states0,    // [CELLS, 2]
                 const float* __restrict__ params,     // [CELLS, 4]
                 float* __restrict__ states_out)       // [T, CELLS, 2]
{
    const int cell = blockIdx.x * blockDim.x + threadIdx.x;

    // ---- parameter transform (once) ----
    const float4 u = reinterpret_cast<const float4*>(params)[cell];
    const float smax = 10.0f  + (500.0f - 10.0f)  * u.x;
    const float k1   = 0.01f  + (0.9f   - 0.01f)  * u.y;
    const float k2   = 0.001f + (0.2f   - 0.001f) * u.z;
    const float kb   = 0.001f + (0.1f   - 0.001f) * u.w;

    const float inv_smax = 1.0f / smax;
    const float c1 = 1.0f - k1 - k2;   // S1 retention (excl. ET)
    const float c2 = 1.0f - kb;        // S2 retention

    float2 s0 = reinterpret_cast<const float2*>(states0)[cell];
    float S1 = s0.x;
    float S2 = s0.y;

    const float2* __restrict__ F  = reinterpret_cast<const float2*>(forcings) + cell;
    float2*       __restrict__ ST = reinterpret_cast<float2*>(states_out)     + cell;

    // ---- double-buffered register prefetch of forcings ----
    float2 buf[2][CHUNK];
#pragma unroll
    for (int i = 0; i < CHUNK; i++)
        buf[0][i] = F[i * CELLS];

    int pb = 0;
#pragma unroll 1
    for (int c = 0; c < TT / CHUNK; c++) {
        // prefetch next chunk (independent of the state chain)
        if (c + 1 < TT / CHUNK) {
            const float2* Fn = F + (c + 1) * CHUNK * CELLS;
#pragma unroll
            for (int i = 0; i < CHUNK; i++)
                buf[pb ^ 1][i] = Fn[i * CELLS];
        }

        float2* STc = ST + c * CHUNK * CELLS;
#pragma unroll
        for (int i = 0; i < CHUNK; i++) {
            const float P   = buf[pb][i].x;
            const float PET = buf[pb][i].y;
            const float a   = PET * inv_smax;      // off-chain

            const float x  = S1 * a;               // chain op 1
            const float et = fminf(x, PET);        // chain op 2
            const float y  = fmaf(S1, c1, P);      // parallel w/ op 1
            const float perc = k2 * S1;            // parallel

            S1 = fmaxf(y - et, 0.0f);              // chain ops 3,4
            S2 = fmaxf(fmaf(S2, c2, perc), 0.0f);  // side chain

            STc[i * CELLS] = make_float2(S1, S2);
        }
        pb ^= 1;
    }
}

// ---------------------------------------------------------------------------
// Kernel B: fluxes from (shifted) states. Fully parallel, memory-bound.
//   flux_t = f(states_{t-1}, forcings_t, params), states_{-1} = states0
// ---------------------------------------------------------------------------
__global__ __launch_bounds__(256)
void flux_kernel(const float* __restrict__ forcings,   // [T, CELLS, 2]
                 const float* __restrict__ states0,    // [CELLS, 2]
                 const float* __restrict__ params,     // [CELLS, 4]
                 const float* __restrict__ states_seq, // [T, CELLS, 2]
                 float* __restrict__ fluxes)           // [T, CELLS, 4]
{
    const int idx = blockIdx.x * blockDim.x + threadIdx.x; // t*CELLS + cell
    const int cell = idx & (CELLS - 1);
    const int t    = idx >> 11;    // CELLS = 2048 = 2^11

    const float2 f = reinterpret_cast<const float2*>(forcings)[idx];
    const float2 s = (t == 0)
        ? reinterpret_cast<const float2*>(states0)[cell]
        : reinterpret_cast<const float2*>(states_seq)[idx - CELLS];

    const float4 u = reinterpret_cast<const float4*>(params)[cell];
    const float smax = 10.0f  + (500.0f - 10.0f)  * u.x;
    const float k1   = 0.01f  + (0.9f   - 0.01f)  * u.y;
    const float k2   = 0.001f + (0.2f   - 0.001f) * u.z;
    const float kb   = 0.001f + (0.1f   - 0.001f) * u.w;

    const float frac = fminf(fmaxf(s.x * (1.0f / smax), 0.0f), 1.0f);
    const float et   = f.y * frac;
    const float q1   = k1 * s.x;
    const float perc = k2 * s.x;
    const float qb   = kb * s.y;

    reinterpret_cast<float4*>(fluxes)[idx] = make_float4(et, q1, perc, qb);
}

extern "C" void kernel_launch(void* const* d_in, const int* in_sizes, int n_in,
                              void* d_out, int out_size)
{
    const float* forcings = (const float*)d_in[0];   // [T,B,H,2]
    const float* states0  = (const float*)d_in[1];   // [B,H,2]
    const float* params   = (const float*)d_in[2];   // [B,H,4]

    float* out = (float*)d_out;
    float* fluxes_out = out;                                   // [T,B,H,4]
    float* states_out = out + (size_t)TT * CELLS * 4;          // [T,B,H,2]

    scan_kernel<<<CELLS / 32, 32>>>(forcings, states0, params, states_out);
    flux_kernel<<<(TT * CELLS) / 256, 256>>>(forcings, states0, params,
                                             states_out, fluxes_out);
}